// round 1
// baseline (speedup 1.0000x reference)
#include <cuda_runtime.h>
#include <math.h>

// TopKRouter: logits = x @ gate_w^T, softmax, top-2 (+renorm), aux loss.
// T=16384 tokens, D=2048, E=64, K=2.
//
// Output layout assumed (tuple flatten-concat, float32):
//   out[0 .. 2T)        top_indices as float
//   out[2T .. 4T)       top_weights (renormalized)
//   out[out_size-1]     aux_loss
//
// GEMM: fp32 via packed fma.rn.f32x2 (2 FMA/inst), 128-token x 64-expert
// tiles, BK=32, double-buffered smem, XOR-swizzled transposed tiles
// (conflict-free STS + vector LDS).

#define NEXP   64
#define TOPK   2
#define BK     32
#define MT     128      // tokens per block
#define NTHR   512
#define MAXBLK 512

__device__ int   g_counts[NEXP];
__device__ float g_wsum_part[MAXBLK * NEXP];
__device__ float g_z_part[MAXBLK];

__device__ __forceinline__ unsigned long long pack2(float v) {
    unsigned long long r;
    unsigned int u = __float_as_uint(v);
    asm("mov.b64 %0, {%1, %1};" : "=l"(r) : "r"(u));
    return r;
}
__device__ __forceinline__ void ffma2(unsigned long long &d,
                                      unsigned long long a,
                                      unsigned long long b) {
    asm("fma.rn.f32x2 %0, %1, %2, %0;" : "+l"(d) : "l"(a), "l"(b));
}
__device__ __forceinline__ void unpack2(unsigned long long v, float &lo, float &hi) {
    unsigned int l, h;
    asm("mov.b64 {%0, %1}, %2;" : "=r"(l), "=r"(h) : "l"(v));
    lo = __uint_as_float(l);
    hi = __uint_as_float(h);
}

__global__ __launch_bounds__(NTHR, 1)
void router_main(const float* __restrict__ X, const float* __restrict__ W,
                 float* __restrict__ out, int T, int D)
{
    __shared__ __align__(16) unsigned char smem_raw[49152];
    float* xs  = (float*)smem_raw;                                 // [2][BK][MT]
    float* wsm = (float*)(smem_raw + 2 * BK * MT * sizeof(float)); // [2][BK][NEXP]

    const int tid = threadIdx.x;
    const int tx  = tid & 15;     // expert group
    const int ty  = tid >> 4;     // token group (0..31)
    const int e0  = tx * 4;
    const int t0  = ty * 4;
    const long tokBase = (long)blockIdx.x * MT;
    const int NC = D / BK;

    // staging (global -> smem) indices: coalesced float4 LDG along D
    const int lrow = tid >> 3;    // 0..63
    const int c4   = tid & 7;     // float4 column within BK
    const int swL  = c4 * 4;      // XOR swizzle for this thread's stores

    unsigned long long acc[2][4]; // [token-pair][expert], f32x2 packed
#pragma unroll
    for (int p = 0; p < 2; p++)
#pragma unroll
        for (int j = 0; j < 4; j++) acc[p][j] = 0ull;

    float4 xreg[2];
    float4 wreg;
    const float* Xb = X + tokBase * D;

    // ---- prologue: load + store chunk 0 ----
#pragma unroll
    for (int i = 0; i < 2; i++)
        xreg[i] = *(const float4*)(Xb + (long)(lrow + 64 * i) * D + c4 * 4);
    wreg = *(const float4*)(W + (long)lrow * D + c4 * 4);

    {
        float* xb2 = xs;
        float* wb2 = wsm;
#pragma unroll
        for (int i = 0; i < 2; i++) {
            int row = lrow + 64 * i;
            int col = row ^ swL;
            xb2[(swL + 0) * MT + col] = xreg[i].x;
            xb2[(swL + 1) * MT + col] = xreg[i].y;
            xb2[(swL + 2) * MT + col] = xreg[i].z;
            xb2[(swL + 3) * MT + col] = xreg[i].w;
        }
        int colw = lrow ^ swL;
        wb2[(swL + 0) * NEXP + colw] = wreg.x;
        wb2[(swL + 1) * NEXP + colw] = wreg.y;
        wb2[(swL + 2) * NEXP + colw] = wreg.z;
        wb2[(swL + 3) * NEXP + colw] = wreg.w;
    }
    __syncthreads();

    // ---- main K loop, double buffered ----
    for (int c = 0; c < NC; ++c) {
        if (c + 1 < NC) {
            const float* xp = Xb + (c + 1) * BK;
#pragma unroll
            for (int i = 0; i < 2; i++)
                xreg[i] = *(const float4*)(xp + (long)(lrow + 64 * i) * D + c4 * 4);
            wreg = *(const float4*)(W + (long)lrow * D + (c + 1) * BK + c4 * 4);
        }
        const float* xb = xs  + (c & 1) * BK * MT;
        const float* wb = wsm + (c & 1) * BK * NEXP;
#pragma unroll
        for (int k = 0; k < BK; k++) {
            const int sw = ((k >> 2) & 7) << 2;
            ulonglong2 xa = *(const ulonglong2*)(xb + k * MT + (t0 ^ sw));
            float4 wv = *(const float4*)(wb + k * NEXP + (e0 ^ sw));
            unsigned long long w0 = pack2(wv.x);
            unsigned long long w1 = pack2(wv.y);
            unsigned long long w2 = pack2(wv.z);
            unsigned long long w3 = pack2(wv.w);
            ffma2(acc[0][0], xa.x, w0);
            ffma2(acc[0][1], xa.x, w1);
            ffma2(acc[0][2], xa.x, w2);
            ffma2(acc[0][3], xa.x, w3);
            ffma2(acc[1][0], xa.y, w0);
            ffma2(acc[1][1], xa.y, w1);
            ffma2(acc[1][2], xa.y, w2);
            ffma2(acc[1][3], xa.y, w3);
        }
        if (c + 1 < NC) {
            float* xb2 = xs  + ((c + 1) & 1) * BK * MT;
            float* wb2 = wsm + ((c + 1) & 1) * BK * NEXP;
#pragma unroll
            for (int i = 0; i < 2; i++) {
                int row = lrow + 64 * i;
                int col = row ^ swL;
                xb2[(swL + 0) * MT + col] = xreg[i].x;
                xb2[(swL + 1) * MT + col] = xreg[i].y;
                xb2[(swL + 2) * MT + col] = xreg[i].z;
                xb2[(swL + 3) * MT + col] = xreg[i].w;
            }
            int colw = lrow ^ swL;
            wb2[(swL + 0) * NEXP + colw] = wreg.x;
            wb2[(swL + 1) * NEXP + colw] = wreg.y;
            wb2[(swL + 2) * NEXP + colw] = wreg.z;
            wb2[(swL + 3) * NEXP + colw] = wreg.w;
        }
        __syncthreads();
    }

    // ---- epilogue: overlay smem ----
    float* lg       = (float*)smem_raw;                                  // [MT][65]
    float* invden_s = (float*)(smem_raw + MT * 65 * sizeof(float));      // [MT]
    float* zs       = invden_s + MT;                                     // [MT]
    int*   hist     = (int*)(zs + MT);                                   // [NEXP]
    float* colred   = (float*)(hist + NEXP);                             // [8][NEXP]

#pragma unroll
    for (int p = 0; p < 2; p++)
#pragma unroll
        for (int j = 0; j < 4; j++) {
            float lo, hi;
            unpack2(acc[p][j], lo, hi);
            lg[(t0 + 2 * p    ) * 65 + e0 + j] = lo;
            lg[(t0 + 2 * p + 1) * 65 + e0 + j] = hi;
        }
    if (tid < NEXP) hist[tid] = 0;
    __syncthreads();

    if (tid < MT) {
        const int t = tid;
        float* row = lg + t * 65;
        float m = row[0];
#pragma unroll 8
        for (int e = 1; e < NEXP; e++) m = fmaxf(m, row[e]);
        float s  = 0.f;
        float b0 = -1.f, b1 = -1.f;
        int   i0 = 0,    i1 = 0;
        for (int e = 0; e < NEXP; e++) {
            float v = expf(row[e] - m);
            row[e] = v;
            s += v;
            if (v > b0) { b1 = b0; i1 = i0; b0 = v; i0 = e; }
            else if (v > b1) { b1 = v; i1 = e; }
        }
        float st  = b0 + b1;
        float wn0 = __fdiv_rn(b0, st);
        float wn1 = __fdiv_rn(b1, st);
        long g = tokBase + t;
        out[2 * g]     = (float)i0;
        out[2 * g + 1] = (float)i1;
        out[2 * (long)T + 2 * g]     = wn0;
        out[2 * (long)T + 2 * g + 1] = wn1;
        invden_s[t] = __frcp_rn(s);
        float lse = m + logf(s);
        zs[t] = lse * lse;
        atomicAdd(&hist[i0], 1);
        atomicAdd(&hist[i1], 1);
    }
    __syncthreads();

    // per-block expert sums of softmax weights (deterministic order)
    {
        const int e   = tid & 63;
        const int seg = tid >> 6;  // 0..7
        float s = 0.f;
#pragma unroll 4
        for (int t = seg * 16; t < seg * 16 + 16; ++t)
            s += lg[t * 65 + e] * invden_s[t];
        colred[seg * NEXP + e] = s;
    }
    __syncthreads();
    if (tid < NEXP) {
        float p = 0.f;
#pragma unroll
        for (int sgi = 0; sgi < 8; ++sgi) p += colred[sgi * NEXP + tid];
        g_wsum_part[blockIdx.x * NEXP + tid] = p;
        atomicAdd(&g_counts[tid], hist[tid]);
        zs[tid] += zs[tid + 64];
    }
    __syncthreads();
    if (tid == 0) {
        float z = 0.f;
        for (int t = 0; t < 64; t++) z += zs[t];
        g_z_part[blockIdx.x] = z;
    }
}

__global__ void router_init() { g_counts[threadIdx.x] = 0; }

__global__ void router_finalize(float* __restrict__ out, int T, int nblk, int aux_pos)
{
    __shared__ float red[NEXP];
    const int e = threadIdx.x;
    float ws = 0.f;
    for (int b = 0; b < nblk; b++) ws += g_wsum_part[b * NEXP + e];
    float f = (float)g_counts[e] / (float)(T * TOPK);
    float P = ws / (float)T;
    red[e] = f * P;
    __syncthreads();
    if (e == 0) {
        float bal = 0.f;
        for (int i = 0; i < NEXP; i++) bal += red[i];
        bal *= (float)NEXP;
        float zsum = 0.f;
        for (int b = 0; b < nblk; b++) zsum += g_z_part[b];
        float z = zsum / (float)T;
        out[aux_pos] = 0.01f * bal + 0.001f * z;
    }
}

extern "C" void kernel_launch(void* const* d_in, const int* in_sizes, int n_in,
                              void* d_out, int out_size)
{
    const float* X = (const float*)d_in[0];
    const float* W = (const float*)d_in[1];
    float* out = (float*)d_out;

    const int D = in_sizes[1] / NEXP;     // 2048
    const int T = in_sizes[0] / D;        // 16384
    const int nblk = T / MT;              // 128

    router_init<<<1, NEXP>>>();
    router_main<<<nblk, NTHR>>>(X, W, out, T, D);
    router_finalize<<<1, NEXP>>>(out, T, nblk, out_size - 1);
}